// round 3
// baseline (speedup 1.0000x reference)
#include <cuda_runtime.h>
#include <cuda_bf16.h>

// Pillar scatter, gather-formulated.
// out[b,f,y,x] = sum_{p: mask[b,p]==1, coord[b,p,1:3]==(y,x)} pillars[b,p,f]
// Shapes fixed by the problem: B=4, P=12000, NF=64, grid 512x512.
//
// Pipeline (one CUDA graph, 4 kernels):
//  1) reset:  zero count grid (4 MB) + overflow counter
//  2) count:  active pillars register themselves in per-cell slot lists
//  3) fill:   stream the 268 MB output once; each element is 0 or the
//             gathered sum over its cell's slot list (coalesced float4 stores,
//             gathers hit L2). This replaces memset + atomic-RMW scatter.
//  4) ovf:    atomic fixup for cells with >K pillars (statistically empty).

#define XS 512
#define YS 512
#define GRID_CELLS (XS * YS)   // 262144 = 2^18
#define BMAX 4
#define NFC 64                 // features (compile-time; checked at launch)
#define K 8                    // slot capacity per cell
#define OVF_CAP 4096

__device__ __align__(16) int d_count[BMAX * GRID_CELLS];
__device__ int d_slots[BMAX * GRID_CELLS * K];
__device__ int d_ovf_n;
__device__ int d_ovf[OVF_CAP * 2];

__global__ void reset_kernel(int n_int4) {
    int i = blockIdx.x * blockDim.x + threadIdx.x;
    if (i == 0) d_ovf_n = 0;
    if (i < n_int4)
        reinterpret_cast<int4*>(d_count)[i] = make_int4(0, 0, 0, 0);
}

__global__ void count_kernel(const int* __restrict__ coord,
                             const int* __restrict__ mask,
                             int BP, int P) {
    int i = blockIdx.x * blockDim.x + threadIdx.x;
    if (i >= BP) return;
    if (mask[i] == 0) return;
    int y = coord[i * 3 + 1];
    int x = coord[i * 3 + 2];
    int b = i / P;
    int cell = b * GRID_CELLS + y * XS + x;
    int pos = atomicAdd(&d_count[cell], 1);
    if (pos < K) {
        d_slots[cell * K + pos] = i;          // global pillar index
    } else {
        int o = atomicAdd(&d_ovf_n, 1);
        if (o < OVF_CAP) { d_ovf[o * 2] = i; d_ovf[o * 2 + 1] = cell; }
    }
}

__device__ __forceinline__ float gather_cell(int cell, int c, int f,
                                             const float* __restrict__ pillars) {
    float v = 0.f;
    c = min(c, K);
    #pragma unroll 2
    for (int s = 0; s < c; s++) {
        int pg = d_slots[cell * K + s];
        v += pillars[(long)pg * NFC + f];
    }
    return v;
}

// One thread per output float4. tid layout matches output linear layout:
// tid = ((b*NF + f) * GRID_CELLS + yx) / 4
__global__ void fill_kernel(const float* __restrict__ pillars,
                            float4* __restrict__ out, int total4) {
    int tid = blockIdx.x * blockDim.x + threadIdx.x;
    if (tid >= total4) return;
    int yx4 = tid & (GRID_CELLS / 4 - 1);          // 2^16 - 1
    int f   = (tid >> 16) & (NFC - 1);
    int b   = tid >> 22;                           // / (NFC * GRID_CELLS / 4)

    int cellbase = b * GRID_CELLS + (yx4 << 2);
    int4 c = *reinterpret_cast<const int4*>(&d_count[cellbase]);

    float4 v = make_float4(0.f, 0.f, 0.f, 0.f);
    if (c.x | c.y | c.z | c.w) {                   // ~9% of threads
        if (c.x) v.x = gather_cell(cellbase + 0, c.x, f, pillars);
        if (c.y) v.y = gather_cell(cellbase + 1, c.y, f, pillars);
        if (c.z) v.z = gather_cell(cellbase + 2, c.z, f, pillars);
        if (c.w) v.w = gather_cell(cellbase + 3, c.w, f, pillars);
    }
    out[tid] = v;
}

__global__ void ovf_kernel(const float* __restrict__ pillars,
                           float* __restrict__ out) {
    int n = d_ovf_n;
    n = min(n, OVF_CAP);
    for (int i = blockIdx.x; i < n; i += gridDim.x) {
        int pg   = d_ovf[i * 2];
        int cell = d_ovf[i * 2 + 1];
        int b  = cell >> 18;                       // / GRID_CELLS
        int yx = cell & (GRID_CELLS - 1);
        for (int f = threadIdx.x; f < NFC; f += blockDim.x)
            atomicAdd(out + (long)b * NFC * GRID_CELLS + (long)f * GRID_CELLS + yx,
                      pillars[(long)pg * NFC + f]);
    }
}

extern "C" void kernel_launch(void* const* d_in, const int* in_sizes, int n_in,
                              void* d_out, int out_size) {
    const float* pillars = (const float*)d_in[0];   // [B, P, NF]
    const int*   coord   = (const int*)d_in[1];     // [B, P, 3]
    const int*   mask    = (const int*)d_in[2];     // [B, P]

    int BP = in_sizes[2];                           // B * P = 48000
    int B  = (int)((long)out_size / ((long)NFC * GRID_CELLS));
    int P  = BP / B;
    float* out = (float*)d_out;

    // 1) reset bins (B*GRID_CELLS ints as int4)
    int n_int4 = (B * GRID_CELLS) / 4;
    reset_kernel<<<(n_int4 + 255) / 256, 256>>>(n_int4);

    // 2) bin pillars into per-cell slot lists
    count_kernel<<<(BP + 255) / 256, 256>>>(coord, mask, BP, P);

    // 3) fused zero+scatter: stream the whole output once
    int total4 = out_size / 4;
    fill_kernel<<<(total4 + 255) / 256, 256>>>(pillars, (float4*)out, total4);

    // 4) overflow fixup (normally 0 entries)
    ovf_kernel<<<8, 64>>>(pillars, out);
}